// round 9
// baseline (speedup 1.0000x reference)
#include <cuda_runtime.h>

#define NN 100000
#define NE 1280000
#define D 64
#define NCHUNK ((NN + 1023) / 1024)  // 98 scan chunks
#define NPB 64                        // nodes per block in sage_layer
#define SMS 66                        // sm row stride (even -> 8B-aligned pairs)

// ---- scratch: module-scope device arrays, referenced ONLY inside kernels ----
__device__ int    g_cnt[NN];             // in-degree histogram
__device__ int    g_ptr[NN];             // CSR exclusive offsets
__device__ int    g_pos[NN];             // fill cursors
__device__ int    g_srcl[NE];            // CSR source-node list
__device__ float4 g_h1_4[NN * D / 4];    // layer-1 hidden
__device__ float4 g_h2_4[NN * D / 4];    // fallback h output
__device__ float4 g_WT4[4 * D * D / 4];  // W1l^T, W1r^T, W2l^T, W2r^T
__device__ int    g_is64;                // edge_index dtype flag

typedef unsigned long long ull;

__device__ __forceinline__ ull pack2(float f) {
    ull r;
    unsigned u = __float_as_uint(f);
    asm("mov.b64 %0, {%1, %1};" : "=l"(r) : "r"(u));
    return r;
}
__device__ __forceinline__ void ffma2(ull& acc, ull a, ull b) {
    asm("fma.rn.f32x2 %0, %1, %2, %0;" : "+l"(acc) : "l"(a), "l"(b));
}
__device__ __forceinline__ void unpack2(ull v, float& lo, float& hi) {
    unsigned a, b;
    asm("mov.b64 {%0, %1}, %2;" : "=r"(a), "=r"(b) : "l"(v));
    lo = __uint_as_float(a);
    hi = __uint_as_float(b);
}

__device__ __forceinline__ int load_idx(const void* ei, int pos, int is64) {
    if (is64) return (int)__ldg((const long long*)ei + pos);
    return __ldg((const int*)ei + pos);
}

// ---------------------------------------------------------------------------
// init: zero g_cnt (all blocks); block 0 detects edge dtype; block 1 transposes W.
__global__ void init_kernel(const int* __restrict__ ei32,
                            const float* __restrict__ W1l, const float* __restrict__ W1r,
                            const float* __restrict__ W2l, const float* __restrict__ W2r) {
    int i = blockIdx.x * 1024 + threadIdx.x;
    if (i < NN) g_cnt[i] = 0;

    if (blockIdx.x == 0 && threadIdx.x < 256) {
        // int64 data (values < 2^31) has all odd int32 words 0
        __shared__ int anyNonZero;
        if (threadIdx.x == 0) anyNonZero = 0;
        __syncwarp();
        __syncthreads();
        int w = ei32[2 * threadIdx.x + 1];
        for (int k = 0; k < 3; k++) w |= ei32[2 * (threadIdx.x + 256 * (k + 1)) + 1];
        if (w != 0) anyNonZero = 1;
        __syncthreads();
        if (threadIdx.x == 0) g_is64 = anyNonZero ? 0 : 1;
    } else if (blockIdx.x == 0) {
        __syncthreads();  // keep block 0 barrier-uniform
        __syncthreads();
    }

    if (blockIdx.x == 1) {
        const float* src[4] = {W1l, W1r, W2l, W2r};
        float* WT = (float*)g_WT4;
        for (int m = 0; m < 4; m++) {
            const float* S = src[m];
            float* T = WT + m * (D * D);
            for (int i2 = threadIdx.x; i2 < D * D; i2 += 1024) {
                int j = i2 >> 6, k = i2 & 63;
                T[k * D + j] = S[i2];
            }
        }
    }
}

__global__ void hist_kernel(const void* __restrict__ ei) {
    int e = blockIdx.x * blockDim.x + threadIdx.x;
    if (e >= NE) return;
    int d = load_idx(ei, NE + e, g_is64);
    atomicAdd(&g_cnt[d], 1);
}

// single-block exclusive scan of g_cnt -> g_ptr & g_pos (sequential chunks)
__global__ void scan_kernel() {
    __shared__ int ws[32];
    __shared__ int carry;
    int tid = threadIdx.x;
    int lane = tid & 31, wid = tid >> 5;
    if (tid == 0) carry = 0;
    __syncthreads();
    for (int chunk = 0; chunk < NCHUNK; chunk++) {
        int i = chunk * 1024 + tid;
        int v = (i < NN) ? g_cnt[i] : 0;
        int sv = v;
#pragma unroll
        for (int o = 1; o < 32; o <<= 1) {
            int n = __shfl_up_sync(0xffffffffu, sv, o);
            if (lane >= o) sv += n;
        }
        if (lane == 31) ws[wid] = sv;
        __syncthreads();
        if (wid == 0) {
            int wv = ws[lane];
#pragma unroll
            for (int o = 1; o < 32; o <<= 1) {
                int n = __shfl_up_sync(0xffffffffu, wv, o);
                if (lane >= o) wv += n;
            }
            ws[lane] = wv;
        }
        __syncthreads();
        int off = (wid ? ws[wid - 1] : 0) + carry;
        int excl = off + sv - v;
        if (i < NN) { g_ptr[i] = excl; g_pos[i] = excl; }
        __syncthreads();
        if (tid == 0) carry += ws[31];
        __syncthreads();
    }
}

__global__ void fill_kernel(const void* __restrict__ ei) {
    int e = blockIdx.x * blockDim.x + threadIdx.x;
    if (e >= NE) return;
    int is64 = g_is64;
    int s = load_idx(ei, e, is64);
    int d = load_idx(ei, NE + e, is64);
    int p = atomicAdd(&g_pos[d], 1);
    g_srcl[p] = s;
}

// ---------------------------------------------------------------------------
// Fused layer: CSR gather-mean + hout = relu(mean @ Wl^T + b + feat @ Wr^T)
// 64 nodes/block; 128 threads = 16 channel-groups (q) x 8 slots; each thread
// owns 8 consecutive nodes and 4 channels. Linear phase: packed f32x2 FMA with
// node-pairs as the SIMD axis; each weight fetch feeds 8 nodes.
template <int LAYER, int HPARAM>
__global__ void __launch_bounds__(128) sage_layer(
                           const float* __restrict__ x,
                           const float* __restrict__ b,
                           float* __restrict__ hout_p,
                           const float* __restrict__ Wh,
                           const float* __restrict__ bh,
                           float* __restrict__ out) {
    __shared__ float smM[D * SMS];   // smM[k*SMS + local_node] : mean
    __shared__ float smX[D * SMS];   // smX[k*SMS + local_node] : root feature
    int t = threadIdx.x;
    int q = t & 15, slot = t >> 4;   // slot 0..7
    int node0 = blockIdx.x * NPB;
    int s8 = slot * 8;

    const float* feat = (LAYER == 0) ? x : (const float*)g_h1_4;

    // ---- gather-mean for this thread's 8 nodes, channels 4q..4q+3 ----
#pragma unroll
    for (int i = 0; i < 8; i++) {
        int nl = s8 + i;
        int node = node0 + nl;
        float4 acc = make_float4(0.f, 0.f, 0.f, 0.f);
        float4 xv = make_float4(0.f, 0.f, 0.f, 0.f);
        float rd = 0.f;
        if (node < NN) {
            int beg = __ldg(&g_ptr[node]);
            int cnt = __ldg(&g_cnt[node]);
            int end = beg + cnt;
            int e = beg;
            for (; e + 3 < end; e += 4) {
                int s0 = __ldg(&g_srcl[e + 0]);
                int s1 = __ldg(&g_srcl[e + 1]);
                int s2 = __ldg(&g_srcl[e + 2]);
                int s3 = __ldg(&g_srcl[e + 3]);
                float4 v0 = __ldg((const float4*)(feat + (size_t)s0 * D) + q);
                float4 v1 = __ldg((const float4*)(feat + (size_t)s1 * D) + q);
                float4 v2 = __ldg((const float4*)(feat + (size_t)s2 * D) + q);
                float4 v3 = __ldg((const float4*)(feat + (size_t)s3 * D) + q);
                acc.x += (v0.x + v1.x) + (v2.x + v3.x);
                acc.y += (v0.y + v1.y) + (v2.y + v3.y);
                acc.z += (v0.z + v1.z) + (v2.z + v3.z);
                acc.w += (v0.w + v1.w) + (v2.w + v3.w);
            }
            for (; e < end; e++) {
                int s0 = __ldg(&g_srcl[e]);
                float4 v0 = __ldg((const float4*)(feat + (size_t)s0 * D) + q);
                acc.x += v0.x; acc.y += v0.y; acc.z += v0.z; acc.w += v0.w;
            }
            rd = 1.0f / (float)max(cnt, 1);
            xv = __ldg((const float4*)(feat + (size_t)node * D) + q);
        }
        int c = q * 4;
        smM[(c + 0) * SMS + nl] = acc.x * rd;
        smM[(c + 1) * SMS + nl] = acc.y * rd;
        smM[(c + 2) * SMS + nl] = acc.z * rd;
        smM[(c + 3) * SMS + nl] = acc.w * rd;
        smX[(c + 0) * SMS + nl] = xv.x;
        smX[(c + 1) * SMS + nl] = xv.y;
        smX[(c + 2) * SMS + nl] = xv.z;
        smX[(c + 3) * SMS + nl] = xv.w;
    }
    __syncthreads();

    // ---- linear: 4 channels x 8 nodes (4 pairs) per thread, f32x2 FMA ----
    const float4* wl4 = (const float4*)((const float*)g_WT4 + (2 * LAYER) * (D * D));
    const float4* wr4 = wl4 + (D * D) / 4;
    float4 bb = __ldg((const float4*)b + q);
    ull A[4][4];
#pragma unroll
    for (int p = 0; p < 4; p++) {
        A[p][0] = pack2(bb.x); A[p][1] = pack2(bb.y);
        A[p][2] = pack2(bb.z); A[p][3] = pack2(bb.w);
    }

#pragma unroll 4
    for (int k = 0; k < D; k++) {
        float4 wl = __ldg(wl4 + k * 16 + q);
        float4 wr = __ldg(wr4 + k * 16 + q);
        ull wlj[4] = {pack2(wl.x), pack2(wl.y), pack2(wl.z), pack2(wl.w)};
        ull wrj[4] = {pack2(wr.x), pack2(wr.y), pack2(wr.z), pack2(wr.w)};
#pragma unroll
        for (int p = 0; p < 4; p++) {
            ull m = *(const ull*)&smM[k * SMS + s8 + 2 * p];
            ull xx = *(const ull*)&smX[k * SMS + s8 + 2 * p];
#pragma unroll
            for (int j = 0; j < 4; j++) {
                ffma2(A[p][j], wlj[j], m);
                ffma2(A[p][j], wrj[j], xx);
            }
        }
    }

    // ---- epilogue: unpack, relu, store h, fused head ----
    float o[8][4];  // [node i][channel j]
#pragma unroll
    for (int p = 0; p < 4; p++)
#pragma unroll
        for (int j = 0; j < 4; j++) {
            unpack2(A[p][j], o[2 * p][j], o[2 * p + 1][j]);
        }
#pragma unroll
    for (int i = 0; i < 8; i++)
#pragma unroll
        for (int j = 0; j < 4; j++) o[i][j] = fmaxf(o[i][j], 0.f);

    float* hout;
    if (LAYER == 0)  hout = (float*)g_h1_4;
    else if (HPARAM) hout = hout_p;
    else             hout = (float*)g_h2_4;

#pragma unroll
    for (int i = 0; i < 8; i++) {
        int node = node0 + s8 + i;
        if (node < NN) {
            float4 v = make_float4(o[i][0], o[i][1], o[i][2], o[i][3]);
            ((float4*)(hout + (size_t)node * D))[q] = v;
        }
    }

    if (LAYER == 1) {  // head: out[n] = dot(h[n], Wh) + bh, width-16 reduction
        float4 wh = __ldg((const float4*)Wh + q);
#pragma unroll
        for (int i = 0; i < 8; i++) {
            float p = o[i][0] * wh.x + o[i][1] * wh.y + o[i][2] * wh.z + o[i][3] * wh.w;
            p += __shfl_down_sync(0xffffffffu, p, 8, 16);
            p += __shfl_down_sync(0xffffffffu, p, 4, 16);
            p += __shfl_down_sync(0xffffffffu, p, 2, 16);
            p += __shfl_down_sync(0xffffffffu, p, 1, 16);
            if (q == 0) {
                int node = node0 + s8 + i;
                if (node < NN) out[node] = p + __ldg(bh);
            }
        }
    }
}

// ---------------------------------------------------------------------------
extern "C" void kernel_launch(void* const* d_in, const int* in_sizes, int n_in,
                              void* d_out, int out_size) {
    const float* x   = (const float*)d_in[0];
    const void*  ei  = d_in[1];
    const float* W1l = (const float*)d_in[2];
    const float* W1r = (const float*)d_in[3];
    const float* b1  = (const float*)d_in[4];
    const float* W2l = (const float*)d_in[5];
    const float* W2r = (const float*)d_in[6];
    const float* b2  = (const float*)d_in[7];
    const float* Wh  = (const float*)d_in[8];
    const float* bh  = (const float*)d_in[9];
    float* outp = (float*)d_out;

    const int EG = (NE + 255) / 256;
    const int LG = (NN + NPB - 1) / NPB;

    init_kernel<<<NCHUNK, 1024>>>((const int*)ei, W1l, W1r, W2l, W2r);
    hist_kernel<<<EG, 256>>>(ei);
    scan_kernel<<<1, 1024>>>();
    fill_kernel<<<EG, 256>>>(ei);

    sage_layer<0, 0><<<LG, 128>>>(x, b1, nullptr, nullptr, nullptr, nullptr);
    if (out_size >= NN * (D + 1)) {
        sage_layer<1, 1><<<LG, 128>>>(nullptr, b2, outp + NN, Wh, bh, outp);
    } else {
        sage_layer<1, 0><<<LG, 128>>>(nullptr, b2, nullptr, Wh, bh, outp);
    }
}